// round 13
// baseline (speedup 1.0000x reference)
#include <cuda_runtime.h>
#include <cuda_bf16.h>

// out[b,t,:] = W[onehot_index(X[b,t,:]), :] + pos[t,:]
// X: (2, 2048, 32000) fp32 one-hot. Block-per-row, barrier-free pipelined
// early-exit scan (volatile smem flag), fused W-gather + pos-add epilogue.

#define BATCH 2
#define CTX   2048
#define VOCAB 32000
#define EMB   1024
#define NROWS (BATCH * CTX)              // 4096
#define ROW_F4 (VOCAB / 4)               // 8000 float4 per X row
#define THREADS 256
#define CHUNK_F4 (THREADS * 2)           // 512 float4 = 2048 floats per chunk
#define NCHUNKS ((ROW_F4 + CHUNK_F4 - 1) / CHUNK_F4)   // 16 (last partial)

#define X_ELEMS (BATCH * CTX * VOCAB)    // 131,072,000
#define W_ELEMS (VOCAB * EMB)            // 32,768,000
#define P_ELEMS (CTX * EMB)              // 2,097,152

__device__ __forceinline__ int f4_nonzero(const float4& v) {
    return (v.x != 0.f) | (v.y != 0.f) | (v.z != 0.f) | (v.w != 0.f);
}
__device__ __forceinline__ int f4_lane(const float4& v) {
    return (v.x != 0.f) ? 0 : (v.y != 0.f) ? 1 : (v.z != 0.f) ? 2 : 3;
}

__global__ void __launch_bounds__(THREADS)
embed_fused_kernel(const float4* __restrict__ X4,
                   const float4* __restrict__ W4,
                   const float4* __restrict__ P4,
                   float4* __restrict__ out4) {
    __shared__ int s_u;
    __shared__ volatile int s_found;

    const int row = blockIdx.x;               // b*CTX + t
    const int t   = row & (CTX - 1);
    const int tid = threadIdx.x;

    const float4* xrow = X4 + (long long)row * ROW_F4;

    // pos[t] prefetch: latency hides behind the scan.
    const float4 p = P4[(long long)t * (EMB / 4) + tid];

    if (tid == 0) { s_u = 0; s_found = 0; }
    __syncthreads();                          // init visible before any finder write

    const float4 fz = make_float4(0.f, 0.f, 0.f, 0.f);

    // ---- Pipelined, barrier-free early-exit scan ------------------------
    // Invariant: v0/v1 hold chunk c's data; chunk c+1's loads are issued
    // before testing chunk c, so 2 LDG.128/warp stay in flight continuously.
    float4 v0 = xrow[tid];                    // chunk 0 (full: 512 <= 8000)
    float4 v1 = xrow[tid + THREADS];

    #pragma unroll 1
    for (int c = 0; c < NCHUNKS; ++c) {
        // Prefetch chunk c+1 (guarded: last chunk is partial).
        float4 n0 = fz, n1 = fz;
        if (c + 1 < NCHUNKS) {
            int j0 = (c + 1) * CHUNK_F4 + tid;
            int j1 = j0 + THREADS;
            if (j0 < ROW_F4) n0 = xrow[j0];
            if (j1 < ROW_F4) n1 = xrow[j1];
        }

        // Test current chunk.
        if (f4_nonzero(v0)) {
            s_u = (c * CHUNK_F4 + tid) * 4 + f4_lane(v0);
            __threadfence_block();
            s_found = 1;
        }
        if (f4_nonzero(v1)) {
            s_u = (c * CHUNK_F4 + THREADS + tid) * 4 + f4_lane(v1);
            __threadfence_block();
            s_found = 1;
        }

        if (s_found) break;                   // volatile poll — no barrier

        v0 = n0;
        v1 = n1;
    }

    // Warps that raced past the finder (or exhausted their chunks before the
    // finder's flag landed) spin until the flag is up. Bounded for safety;
    // valid one-hot input always sets it.
    for (int spin = 0; !s_found && spin < (1 << 22); ++spin) { }
    __threadfence_block();                    // acquire: order s_u read after flag

    // ---- Fused epilogue: out[row] = W[u] + pos[t] -----------------------
    const int u = s_u;
    const int c = tid;                        // EMB/4 = 256 float4 per row

    float4 w = W4[(long long)u * (EMB / 4) + c];
    float4 o;
    o.x = w.x + p.x;
    o.y = w.y + p.y;
    o.z = w.z + p.z;
    o.w = w.w + p.w;
    out4[(long long)row * (EMB / 4) + c] = o;
}

extern "C" void kernel_launch(void* const* d_in, const int* in_sizes, int n_in,
                              void* d_out, int out_size) {
    // Resolve inputs by element count (robust to metadata ordering).
    const float4* X4 = nullptr;
    const float4* W4 = nullptr;
    const float4* P4 = nullptr;
    for (int i = 0; i < n_in; ++i) {
        if (in_sizes[i] == X_ELEMS)      X4 = (const float4*)d_in[i];
        else if (in_sizes[i] == W_ELEMS) W4 = (const float4*)d_in[i];
        else if (in_sizes[i] == P_ELEMS) P4 = (const float4*)d_in[i];
    }
    float4* out4 = (float4*)d_out;

    embed_fused_kernel<<<NROWS, THREADS>>>(X4, W4, P4, out4);
}